// round 2
// baseline (speedup 1.0000x reference)
#include <cuda_runtime.h>
#include <cstdint>

#define B_SZ   64
#define KCP    16
#define NDIM   19   // K + 3
#define NPAD   20   // padded coeff rows per batch (16B alignment + even count)
#define HH     512
#define WW     512
#define HWPIX  (HH * WW)

// Per-batch TPS coefficients, padded: [B][NPAD] float2, row 19 = (0,0).
__device__ float2 g_coeff[B_SZ * NPAD];

// ---------------------------------------------------------------------------
// Packed f32x2 helpers (sm_103a): one instruction does both output dims.
// ---------------------------------------------------------------------------
__device__ __forceinline__ unsigned long long pack2(float lo, float hi) {
    unsigned long long r;
    asm("mov.b64 %0, {%1, %2};" : "=l"(r) : "f"(lo), "f"(hi));
    return r;
}
__device__ __forceinline__ unsigned long long fma2(unsigned long long a,
                                                   unsigned long long b,
                                                   unsigned long long c) {
    unsigned long long d;
    asm("fma.rn.f32x2 %0, %1, %2, %3;" : "=l"(d) : "l"(a), "l"(b), "l"(c));
    return d;
}
__device__ __forceinline__ unsigned long long add2(unsigned long long a,
                                                   unsigned long long b) {
    unsigned long long d;
    asm("add.rn.f32x2 %0, %1, %2;" : "=l"(d) : "l"(a), "l"(b));
    return d;
}

// ---------------------------------------------------------------------------
// Setup kernel (1 block): build delta(19x19), invert via Gauss-Jordan with
// partial pivoting (fp64), then coeff[b] = inv_delta @ [sp_b ; 0].
// ---------------------------------------------------------------------------
__device__ __forceinline__ double cpx_d(int k) { return -1.0 + (double)(k >> 2) * (2.0 / 3.0); }
__device__ __forceinline__ double cpy_d(int k) { return -1.0 + (double)(k & 3) * (2.0 / 3.0); }

__global__ void __launch_bounds__(256) tps_setup_kernel(const float* __restrict__ sp) {
    __shared__ double M[NDIM][2 * NDIM];
    __shared__ double fac[NDIM];
    __shared__ int s_piv;

    const int tid = threadIdx.x;
    const int nt  = blockDim.x;

    // Build augmented [delta | I]
    for (int idx = tid; idx < NDIM * 2 * NDIM; idx += nt) {
        int r = idx / (2 * NDIM), c = idx % (2 * NDIM);
        double v = 0.0;
        if (c >= NDIM) {
            v = (c - NDIM == r) ? 1.0 : 0.0;
        } else if (r < KCP && c < KCP) {
            double dx = cpx_d(r) - cpx_d(c);
            double dy = cpy_d(r) - cpy_d(c);
            double r2 = dx * dx + dy * dy;
            v = r2 * log(r2 + 1e-6);
        } else if (r < KCP) {
            v = (c == KCP) ? 1.0 : ((c == KCP + 1) ? cpx_d(r) : cpy_d(r));
        } else if (c < KCP) {
            v = (r == KCP) ? 1.0 : ((r == KCP + 1) ? cpx_d(c) : cpy_d(c));
        }
        M[r][c] = v;
    }
    __syncthreads();

    // Gauss-Jordan with partial pivoting
    for (int p = 0; p < NDIM; p++) {
        if (tid == 0) {
            int best = p;
            double bm = fabs(M[p][p]);
            for (int r = p + 1; r < NDIM; r++) {
                double m = fabs(M[r][p]);
                if (m > bm) { bm = m; best = r; }
            }
            s_piv = best;
        }
        __syncthreads();
        const int piv = s_piv;
        for (int c = tid; c < 2 * NDIM; c += nt) {
            if (piv != p) {
                double t = M[p][c];
                M[p][c] = M[piv][c];
                M[piv][c] = t;
            }
        }
        __syncthreads();
        const double pd = M[p][p];
        __syncthreads();
        const double inv = 1.0 / pd;
        for (int c = tid; c < 2 * NDIM; c += nt) M[p][c] *= inv;
        __syncthreads();
        for (int r = tid; r < NDIM; r += nt) fac[r] = (r == p) ? 0.0 : M[r][p];
        __syncthreads();
        for (int idx = tid; idx < NDIM * 2 * NDIM; idx += nt) {
            int r = idx / (2 * NDIM), c = idx % (2 * NDIM);
            M[r][c] -= fac[r] * M[p][c];
        }
        __syncthreads();
    }

    // coeff[b][i][d] = sum_{j<16} inv[i][j] * sp[b][j][d]
    for (int idx = tid; idx < B_SZ * NDIM; idx += nt) {
        int b = idx / NDIM, i = idx % NDIM;
        const float* spb = sp + b * (KCP * 2);
        double ax = 0.0, ay = 0.0;
        #pragma unroll
        for (int j = 0; j < KCP; j++) {
            double w = M[i][NDIM + j];
            ax += w * (double)spb[j * 2 + 0];
            ay += w * (double)spb[j * 2 + 1];
        }
        g_coeff[b * NPAD + i] = make_float2((float)ax, (float)ay);
    }
    // zero pad row 19
    for (int b = tid; b < B_SZ; b += nt) {
        g_coeff[b * NPAD + NDIM] = make_float2(0.0f, 0.0f);
    }
}

// ---------------------------------------------------------------------------
// Main kernel: 1 thread = 1 pixel; compute the 19-element basis once, then
// loop over all 64 batches with packed f32x2 FMAs against shared coeffs.
// ---------------------------------------------------------------------------
__global__ void __launch_bounds__(256) tps_main_kernel(float2* __restrict__ out) {
    __shared__ __align__(16) float2 s_coeff[B_SZ * NPAD];  // 10 KB

    const int tid = threadIdx.x;
    for (int idx = tid; idx < B_SZ * NPAD; idx += 256) s_coeff[idx] = g_coeff[idx];
    __syncthreads();

    const int n = blockIdx.x * 256 + tid;
    const int w = n & (WW - 1);
    const int h = n >> 9;
    const float X = fmaf((float)w, 2.0f / (float)(WW - 1), -1.0f);
    const float Y = fmaf((float)h, 2.0f / (float)(HH - 1), -1.0f);

    unsigned long long u2[NPAD];
    #pragma unroll
    for (int k = 0; k < KCP; k++) {
        const float cx = -1.0f + (float)(k >> 2) * (2.0f / 3.0f);
        const float cy = -1.0f + (float)(k & 3) * (2.0f / 3.0f);
        float dx = X - cx;
        float dy = Y - cy;
        float r2 = fmaf(dx, dx, dy * dy);
        float u  = r2 * __logf(r2 + 1e-6f);
        u2[k] = pack2(u, u);
    }
    u2[16] = pack2(1.0f, 1.0f);
    u2[17] = pack2(X, X);
    u2[18] = pack2(Y, Y);
    u2[19] = 0ULL;

    unsigned long long* __restrict__ outp = reinterpret_cast<unsigned long long*>(out);

    #pragma unroll 2
    for (int b = 0; b < B_SZ; b++) {
        const ulonglong2* cc = reinterpret_cast<const ulonglong2*>(s_coeff + b * NPAD);
        unsigned long long a0 = 0ULL, a1 = 0ULL;
        #pragma unroll
        for (int j = 0; j < NPAD / 2; j++) {
            ulonglong2 c = cc[j];                 // LDS.128 broadcast
            a0 = fma2(u2[2 * j + 0], c.x, a0);
            a1 = fma2(u2[2 * j + 1], c.y, a1);
        }
        outp[(size_t)b * HWPIX + n] = add2(a0, a1);
    }
}

// ---------------------------------------------------------------------------
extern "C" void kernel_launch(void* const* d_in, const int* in_sizes, int n_in,
                              void* d_out, int out_size) {
    const float* sp = (const float*)d_in[0];   // [64, 16, 2] fp32
    float2* out = (float2*)d_out;              // [64, 512, 512, 2] fp32

    tps_setup_kernel<<<1, 256>>>(sp);
    tps_main_kernel<<<HWPIX / 256, 256>>>(out);
}

// round 5
// speedup vs baseline: 2.6891x; 2.6891x over previous
#include <cuda_runtime.h>
#include <cstdint>
#include <cmath>

#define B_SZ   64
#define KCP    16
#define NDIM   19   // K + 3
#define NPAD   20   // padded coeff rows per batch (16B alignment)
#define HH     512
#define WW     512
#define HWPIX  (HH * WW)

// Per-batch TPS coefficients, padded: [B][NPAD] float2, row 19 = (0,0).
__device__ float2 g_coeff[B_SZ * NPAD];

// inv_delta[:, :16] passed by value (computed on host — input-independent).
struct InvW {
    float w[NDIM][KCP];
};

// ---------------------------------------------------------------------------
// Packed f32x2 helpers (sm_103a).
// ---------------------------------------------------------------------------
__device__ __forceinline__ unsigned long long pack2(float lo, float hi) {
    unsigned long long r;
    asm("mov.b64 %0, {%1, %2};" : "=l"(r) : "f"(lo), "f"(hi));
    return r;
}
__device__ __forceinline__ unsigned long long fma2(unsigned long long a,
                                                   unsigned long long b,
                                                   unsigned long long c) {
    unsigned long long d;
    asm("fma.rn.f32x2 %0, %1, %2, %3;" : "=l"(d) : "l"(a), "l"(b), "l"(c));
    return d;
}
__device__ __forceinline__ unsigned long long add2(unsigned long long a,
                                                   unsigned long long b) {
    unsigned long long d;
    asm("add.rn.f32x2 %0, %1, %2;" : "=l"(d) : "l"(a), "l"(b));
    return d;
}

// ---------------------------------------------------------------------------
// Tiny coeff kernel: coeff[b][i] = sum_{j<16} invW[i][j] * sp[b][j][:]
// ---------------------------------------------------------------------------
__global__ void __launch_bounds__(256) tps_coeff_kernel(InvW inv, const float* __restrict__ sp) {
    const int tid = threadIdx.x;
    for (int idx = tid; idx < B_SZ * NDIM; idx += 256) {
        const int b = idx / NDIM, i = idx % NDIM;
        const float* spb = sp + b * (KCP * 2);
        float ax = 0.0f, ay = 0.0f;
        #pragma unroll
        for (int j = 0; j < KCP; j++) {
            const float w = inv.w[i][j];
            ax = fmaf(w, spb[j * 2 + 0], ax);
            ay = fmaf(w, spb[j * 2 + 1], ay);
        }
        g_coeff[b * NPAD + i] = make_float2(ax, ay);
    }
    for (int b = tid; b < B_SZ; b += 256) {
        g_coeff[b * NPAD + NDIM] = make_float2(0.0f, 0.0f);
    }
}

// ---------------------------------------------------------------------------
// Main kernel: 1 thread = 2 adjacent-w pixels. Each coeff LDS.128 feeds both
// pixels (halves L1 traffic vs 1 pixel/thread); pair output -> one STG.128.
// ---------------------------------------------------------------------------
__global__ void __launch_bounds__(256) tps_main_kernel(ulonglong2* __restrict__ out) {
    __shared__ __align__(16) float2 s_coeff[B_SZ * NPAD];  // 10 KB

    const int tid = threadIdx.x;
    for (int idx = tid; idx < B_SZ * NPAD; idx += 256) s_coeff[idx] = g_coeff[idx];
    __syncthreads();

    const int t  = blockIdx.x * 256 + tid;   // pixel-pair index
    const int n0 = t * 2;
    const int w0 = n0 & (WW - 1);
    const int h  = n0 >> 9;
    const float X0 = fmaf((float)w0, 2.0f / (float)(WW - 1), -1.0f);
    const float X1 = X0 + 2.0f / (float)(WW - 1);
    const float Y  = fmaf((float)h, 2.0f / (float)(HH - 1), -1.0f);

    // RBF basis for both pixels, each value duplicated into both f32x2 lanes.
    unsigned long long u0[KCP], u1[KCP];
    #pragma unroll
    for (int k = 0; k < KCP; k++) {
        const float cx = -1.0f + (float)(k >> 2) * (2.0f / 3.0f);
        const float cy = -1.0f + (float)(k & 3) * (2.0f / 3.0f);
        const float dy  = Y - cy;
        const float dy2 = dy * dy;
        {
            float dx = X0 - cx;
            float r2 = fmaf(dx, dx, dy2);
            float u  = r2 * __logf(r2 + 1e-6f);
            u0[k] = pack2(u, u);
        }
        {
            float dx = X1 - cx;
            float r2 = fmaf(dx, dx, dy2);
            float u  = r2 * __logf(r2 + 1e-6f);
            u1[k] = pack2(u, u);
        }
    }
    const unsigned long long X0d = pack2(X0, X0);
    const unsigned long long X1d = pack2(X1, X1);
    const unsigned long long Yd  = pack2(Y, Y);

    #pragma unroll 4
    for (int b = 0; b < B_SZ; b++) {
        const ulonglong2* cc = reinterpret_cast<const ulonglong2*>(s_coeff + b * NPAD);
        // Affine part: rows 16 (const), 17 (x), 18 (y)
        const ulonglong2 c8 = cc[8];   // rows 16, 17
        const ulonglong2 c9 = cc[9];   // rows 18, pad
        unsigned long long a0 = fma2(X0d, c8.y, c8.x);
        unsigned long long a1 = fma2(X1d, c8.y, c8.x);
        a0 = fma2(Yd, c9.x, a0);
        a1 = fma2(Yd, c9.x, a1);
        unsigned long long b0 = 0ULL, b1 = 0ULL;
        #pragma unroll
        for (int j = 0; j < 8; j++) {
            const ulonglong2 c = cc[j];           // rows 2j, 2j+1 (broadcast LDS.128)
            a0 = fma2(u0[2 * j + 0], c.x, a0);
            b0 = fma2(u0[2 * j + 1], c.y, b0);
            a1 = fma2(u1[2 * j + 0], c.x, a1);
            b1 = fma2(u1[2 * j + 1], c.y, b1);
        }
        ulonglong2 r;
        r.x = add2(a0, b0);
        r.y = add2(a1, b1);
        out[(size_t)b * (HWPIX / 2) + t] = r;     // 16B-aligned STG.128
    }
}

// ---------------------------------------------------------------------------
// Host: build delta(19x19), invert (Gauss-Jordan, partial pivoting, fp64).
// Input-independent -> runs on CPU at capture time; result rides in as a
// kernel parameter.
// ---------------------------------------------------------------------------
static inline double h_cpx(int k) { return -1.0 + (double)(k >> 2) * (2.0 / 3.0); }
static inline double h_cpy(int k) { return -1.0 + (double)(k & 3) * (2.0 / 3.0); }

static void build_invw(InvW* out) {
    double M[NDIM][2 * NDIM];
    for (int r = 0; r < NDIM; r++)
        for (int c = 0; c < 2 * NDIM; c++) {
            double v = 0.0;
            if (c >= NDIM) {
                v = (c - NDIM == r) ? 1.0 : 0.0;
            } else if (r < KCP && c < KCP) {
                double dx = h_cpx(r) - h_cpx(c);
                double dy = h_cpy(r) - h_cpy(c);
                double r2 = dx * dx + dy * dy;
                v = r2 * log(r2 + 1e-6);
            } else if (r < KCP) {
                v = (c == KCP) ? 1.0 : ((c == KCP + 1) ? h_cpx(r) : h_cpy(r));
            } else if (c < KCP) {
                v = (r == KCP) ? 1.0 : ((r == KCP + 1) ? h_cpx(c) : h_cpy(c));
            }
            M[r][c] = v;
        }

    for (int p = 0; p < NDIM; p++) {
        int best = p;
        double bm = fabs(M[p][p]);
        for (int r = p + 1; r < NDIM; r++) {
            double m = fabs(M[r][p]);
            if (m > bm) { bm = m; best = r; }
        }
        if (best != p)
            for (int c = 0; c < 2 * NDIM; c++) {
                double tv = M[p][c]; M[p][c] = M[best][c]; M[best][c] = tv;
            }
        const double inv = 1.0 / M[p][p];
        for (int c = 0; c < 2 * NDIM; c++) M[p][c] *= inv;
        for (int r = 0; r < NDIM; r++) {
            if (r == p) continue;
            const double f = M[r][p];
            if (f == 0.0) continue;
            for (int c = 0; c < 2 * NDIM; c++) M[r][c] -= f * M[p][c];
        }
    }

    for (int i = 0; i < NDIM; i++)
        for (int j = 0; j < KCP; j++)
            out->w[i][j] = (float)M[i][NDIM + j];
}

// ---------------------------------------------------------------------------
extern "C" void kernel_launch(void* const* d_in, const int* in_sizes, int n_in,
                              void* d_out, int out_size) {
    const float* sp = (const float*)d_in[0];        // [64, 16, 2] fp32
    ulonglong2* out = (ulonglong2*)d_out;           // [64, 512, 512, 2] fp32

    InvW inv;
    build_invw(&inv);                               // host-side, capture-time only

    tps_coeff_kernel<<<1, 256>>>(inv, sp);
    tps_main_kernel<<<(HWPIX / 2) / 256, 256>>>(out);
}